// round 1
// baseline (speedup 1.0000x reference)
#include <cuda_runtime.h>

// Seq2seq LSTM, persistent single-kernel implementation.
// B=32, H=2048, T_IN=128, T_OUT=64, IO=1.
// 128 blocks x 256 threads, all resident -> software grid barrier per step.
// Each thread owns (2 batches x 1 hidden unit x 4 gates); cell state c stays in registers.

#define GRID   128
#define NTHR   256
#define BSZ    32
#define HID    2048
#define TIN    128
#define TOUT   64
#define UPB    16            // hidden units per block (128*16 = 2048)
#define KC     256           // k-chunk staged in smem
#define KSTR   260           // padded stride (260*4 = 1040 bytes, 16B aligned, bank-skewed)
#define TSTEPS (TIN + TOUT)  // 192

__device__ __align__(16) float g_hA[BSZ * HID];
__device__ __align__(16) float g_hB[BSZ * HID];
__device__ float    g_yblk[GRID * BSZ];
__device__ unsigned g_bar;
__device__ unsigned g_fin;

// Packed dual-FMA: d.{x,y} += a.{x,y} * b.{x,y}  (Blackwell f32x2 pipe, 2 MACs/lane-op)
__device__ __forceinline__ void fma2(unsigned long long& d,
                                     unsigned long long a,
                                     unsigned long long b) {
    asm("fma.rn.f32x2 %0, %1, %2, %0;" : "+l"(d) : "l"(a), "l"(b));
}

__device__ __forceinline__ float hsum2(unsigned long long v) {
    return __uint_as_float((unsigned)v) + __uint_as_float((unsigned)(v >> 32));
}

__device__ __forceinline__ float sigmoidf(float v) {
    return 1.0f / (1.0f + __expf(-v));
}

// Grid-wide barrier: monotonically increasing counter, reset at kernel end.
__device__ __forceinline__ void grid_barrier(int n) {
    __syncthreads();
    if (threadIdx.x == 0) {
        __threadfence();
        atomicAdd(&g_bar, 1u);
        unsigned target = (unsigned)n * GRID;
        unsigned v;
        do {
            asm volatile("ld.acquire.gpu.global.u32 %0, [%1];"
                         : "=r"(v) : "l"(&g_bar) : "memory");
        } while (v < target);
    }
    __syncthreads();
}

__global__ void __launch_bounds__(NTHR, 1)
lstm_seq2seq_kernel(const float* __restrict__ x,
                    const float* __restrict__ eWih, const float* __restrict__ eWhh,
                    const float* __restrict__ eb,
                    const float* __restrict__ dWih, const float* __restrict__ dWhh,
                    const float* __restrict__ db,
                    const float* __restrict__ fcW,  const float* __restrict__ fcb,
                    float* __restrict__ out) {
    __shared__ __align__(16) float h_s[BSZ][KSTR];
    __shared__ float ypart[UPB][BSZ + 1];
    __shared__ float y_s[BSZ];

    const int tid = threadIdx.x;
    const int blk = blockIdx.x;
    const int b1  = tid & 15;        // batches 0..15
    const int b2  = b1 + 16;         // batches 16..31
    const int ul  = tid >> 4;        // 0..15 local unit
    const int u   = blk * UPB + ul;  // global hidden unit

    // zero initial h (buffer A); c lives in registers
    g_hA[b1 * HID + u] = 0.0f;
    g_hA[b2 * HID + u] = 0.0f;

    float c1 = 0.0f, c2 = 0.0f;
    const float fcb0 = fcb[0];
    const float fcw  = fcW[u];

    // per-phase weight state
    const float* r0 = 0; const float* r1 = 0; const float* r2 = 0; const float* r3 = 0;
    float wih0 = 0, wih1 = 0, wih2 = 0, wih3 = 0;
    float bv0 = 0, bv1 = 0, bv2 = 0, bv3 = 0;

    int bars = 0;
    grid_barrier(++bars);  // h init visible everywhere

    float inp1 = 0.0f, inp2 = 0.0f;

    for (int t = 0; t < TSTEPS; ++t) {
        const bool enc = (t < TIN);
        if (t == 0 || t == TIN) {
            const float* Wih = enc ? eWih : dWih;
            const float* Whh = enc ? eWhh : dWhh;
            const float* bv  = enc ? eb   : db;
            const size_t HH = (size_t)HID * HID;
            r0 = Whh + (size_t)u * HID;
            r1 = r0 + HH; r2 = r1 + HH; r3 = r2 + HH;
            wih0 = Wih[u]; wih1 = Wih[HID + u]; wih2 = Wih[2 * HID + u]; wih3 = Wih[3 * HID + u];
            bv0  = bv[u];  bv1  = bv[HID + u];  bv2  = bv[2 * HID + u];  bv3  = bv[3 * HID + u];
        }

        // decoder input: reduce y from previous step's partials
        if (!enc && t > TIN) {
            if (tid < BSZ) {
                float s = fcb0;
                #pragma unroll 8
                for (int g = 0; g < GRID; ++g) s += g_yblk[g * BSZ + tid];
                y_s[tid] = s;
                if (blk == 0) out[tid * TOUT + (t - 1 - TIN)] = s;
            }
            __syncthreads();
            inp1 = y_s[b1];
            inp2 = y_s[b2];
        } else if (t == TIN) {
            inp1 = x[b1 * TIN + (TIN - 1)];
            inp2 = x[b2 * TIN + (TIN - 1)];
        } else {
            inp1 = x[b1 * TIN + t];
            inp2 = x[b2 * TIN + t];
        }

        const float* hin = (t & 1) ? g_hB : g_hA;
        float*       hout = (t & 1) ? g_hA : g_hB;

        // accumulate gates: [i,f,g,o] x [b1,b2], packed pairwise over k
        unsigned long long a00 = 0, a10 = 0, a20 = 0, a30 = 0;
        unsigned long long a01 = 0, a11 = 0, a21 = 0, a31 = 0;

        for (int kc = 0; kc < HID; kc += KC) {
            __syncthreads();  // protect h_s reuse
            // cooperative stage of h chunk: 32 rows x 256 cols
            #pragma unroll
            for (int i = 0; i < 8; ++i) {
                int f4 = tid + i * NTHR;       // float4 index, 0..2047
                int bb = f4 >> 6;              // row (batch)
                int c4 = f4 & 63;              // float4 col within chunk
                float4 v = *reinterpret_cast<const float4*>(hin + bb * HID + kc + c4 * 4);
                *reinterpret_cast<float4*>(&h_s[bb][c4 * 4]) = v;
            }
            __syncthreads();

            const float* p0 = r0 + kc;
            const float* p1 = r1 + kc;
            const float* p2 = r2 + kc;
            const float* p3 = r3 + kc;

            #pragma unroll 4
            for (int k4 = 0; k4 < KC; k4 += 4) {
                ulonglong2 w0 = *reinterpret_cast<const ulonglong2*>(p0 + k4);
                ulonglong2 w1 = *reinterpret_cast<const ulonglong2*>(p1 + k4);
                ulonglong2 w2 = *reinterpret_cast<const ulonglong2*>(p2 + k4);
                ulonglong2 w3 = *reinterpret_cast<const ulonglong2*>(p3 + k4);
                ulonglong2 hv1 = *reinterpret_cast<const ulonglong2*>(&h_s[b1][k4]);
                ulonglong2 hv2 = *reinterpret_cast<const ulonglong2*>(&h_s[b2][k4]);
                fma2(a00, w0.x, hv1.x); fma2(a10, w1.x, hv1.x);
                fma2(a20, w2.x, hv1.x); fma2(a30, w3.x, hv1.x);
                fma2(a01, w0.x, hv2.x); fma2(a11, w1.x, hv2.x);
                fma2(a21, w2.x, hv2.x); fma2(a31, w3.x, hv2.x);
                fma2(a00, w0.y, hv1.y); fma2(a10, w1.y, hv1.y);
                fma2(a20, w2.y, hv1.y); fma2(a30, w3.y, hv1.y);
                fma2(a01, w0.y, hv2.y); fma2(a11, w1.y, hv2.y);
                fma2(a21, w2.y, hv2.y); fma2(a31, w3.y, hv2.y);
            }
        }

        // LSTM cell update (b1)
        {
            float gi = hsum2(a00) + inp1 * wih0 + bv0;
            float gf = hsum2(a10) + inp1 * wih1 + bv1;
            float gg = hsum2(a20) + inp1 * wih2 + bv2;
            float go = hsum2(a30) + inp1 * wih3 + bv3;
            float iv = sigmoidf(gi), fv = sigmoidf(gf), gv = tanhf(gg), ov = sigmoidf(go);
            c1 = fv * c1 + iv * gv;
            float hn = ov * tanhf(c1);
            hout[b1 * HID + u] = hn;
            if (!enc) ypart[ul][b1] = hn * fcw;
        }
        // LSTM cell update (b2)
        {
            float gi = hsum2(a01) + inp2 * wih0 + bv0;
            float gf = hsum2(a11) + inp2 * wih1 + bv1;
            float gg = hsum2(a21) + inp2 * wih2 + bv2;
            float go = hsum2(a31) + inp2 * wih3 + bv3;
            float iv = sigmoidf(gi), fv = sigmoidf(gf), gv = tanhf(gg), ov = sigmoidf(go);
            c2 = fv * c2 + iv * gv;
            float hn = ov * tanhf(c2);
            hout[b2 * HID + u] = hn;
            if (!enc) ypart[ul][b2] = hn * fcw;
        }

        if (!enc) {
            __syncthreads();
            if (tid < BSZ) {
                float s = 0.0f;
                #pragma unroll
                for (int uu = 0; uu < UPB; ++uu) s += ypart[uu][tid];
                g_yblk[blk * BSZ + tid] = s;
            }
        }

        grid_barrier(++bars);
    }

    // final output y_63
    if (blk == 0 && tid < BSZ) {
        float s = fcb0;
        #pragma unroll 8
        for (int g = 0; g < GRID; ++g) s += g_yblk[g * BSZ + tid];
        out[tid * TOUT + (TOUT - 1)] = s;
    }

    // barrier-counter cleanup for next launch (graph replay)
    __syncthreads();
    if (tid == 0) {
        unsigned o = atomicAdd(&g_fin, 1u);
        if (o == GRID - 1) {
            g_bar = 0u;
            g_fin = 0u;
            __threadfence();
        }
    }
}

extern "C" void kernel_launch(void* const* d_in, const int* in_sizes, int n_in,
                              void* d_out, int out_size) {
    const float* x    = (const float*)d_in[0];
    // d_in[1] = target (unused, teacher_forcing_ratio = 0)
    const float* eWih = (const float*)d_in[2];
    const float* eWhh = (const float*)d_in[3];
    const float* eb   = (const float*)d_in[4];
    const float* dWih = (const float*)d_in[5];
    const float* dWhh = (const float*)d_in[6];
    const float* db   = (const float*)d_in[7];
    const float* fcW  = (const float*)d_in[8];
    const float* fcb  = (const float*)d_in[9];
    float* out = (float*)d_out;

    lstm_seq2seq_kernel<<<GRID, NTHR>>>(x, eWih, eWhh, eb, dWih, dWhh, db, fcW, fcb, out);
}